// round 2
// baseline (speedup 1.0000x reference)
#include <cuda_runtime.h>
#include <cstdint>

// ============================ problem sizes ============================
#define BATCH 4096
#define INF   1024
#define OUTF  1024
#define KBASIS 8
#define KDIM  (INF * KBASIS)   // 8192

// ======================= device scratch (no allocs) ====================
__device__ float g_A[(size_t)BATCH * KDIM];   // tf32-rounded basis, K-major [4096 x 8192]
__device__ float g_W[(size_t)OUTF * KDIM];    // tf32-rounded weights,      [1024 x 8192]

// ============================ PTX helpers ==============================
__device__ __forceinline__ uint32_t smem_u32(const void* p) {
    uint32_t a;
    asm("{ .reg .u64 t; cvta.to.shared.u64 t, %1; cvt.u32.u64 %0, t; }" : "=r"(a) : "l"(p));
    return a;
}

#define CP_ASYNC_CG16(smem, gptr) \
    asm volatile("cp.async.cg.shared.global [%0], [%1], 16;" :: "r"(smem), "l"(gptr) : "memory")

#define CP_ASYNC_COMMIT() \
    asm volatile("cp.async.commit_group;" ::: "memory")

#define CP_ASYNC_WAIT(n) \
    asm volatile("cp.async.wait_group %0;" :: "n"(n) : "memory")

// m16n8k8 tf32 MMA (row-major A, col-major B), fp32 accumulate in place.
#define MMA_TF32(d, a, b) \
    asm volatile("mma.sync.aligned.m16n8k8.row.col.f32.tf32.tf32.f32 " \
        "{%0,%1,%2,%3}, {%4,%5,%6,%7}, {%8,%9}, {%0,%1,%2,%3};" \
        : "+f"((d)[0]), "+f"((d)[1]), "+f"((d)[2]), "+f"((d)[3]) \
        : "r"((a)[0]), "r"((a)[1]), "r"((a)[2]), "r"((a)[3]), \
          "r"((b)[0]), "r"((b)[1]))

__device__ __forceinline__ float tf32_rna(float v) {
    uint32_t u;
    asm("cvt.rna.tf32.f32 %0, %1;" : "=r"(u) : "f"(v));
    return __uint_as_float(u);
}

// ======================= kernel 1: Chebyshev basis =====================
__global__ void __launch_bounds__(256) basis_kernel(const float* __restrict__ x) {
    int idx = blockIdx.x * blockDim.x + threadIdx.x;   // idx = b*INF + i
    if (idx >= BATCH * INF) return;
    float t = tanhf(x[idx]);
    float T[KBASIS];
    T[0] = 1.0f;
    T[1] = t;
#pragma unroll
    for (int k = 2; k < KBASIS; k++) T[k] = 2.0f * t * T[k - 1] - T[k - 2];

    float4 v0, v1;
    v0.x = tf32_rna(T[0]); v0.y = tf32_rna(T[1]); v0.z = tf32_rna(T[2]); v0.w = tf32_rna(T[3]);
    v1.x = tf32_rna(T[4]); v1.y = tf32_rna(T[5]); v1.z = tf32_rna(T[6]); v1.w = tf32_rna(T[7]);
    float4* dst = reinterpret_cast<float4*>(&g_A[(size_t)idx * KBASIS]);
    dst[0] = v0;
    dst[1] = v1;
}

// ===================== kernel 2: round weights to tf32 =================
__global__ void __launch_bounds__(256) wconv_kernel(const float* __restrict__ w) {
    int idx = blockIdx.x * blockDim.x + threadIdx.x;   // float4 index
    if (idx >= (OUTF * KDIM) / 4) return;
    float4 v = reinterpret_cast<const float4*>(w)[idx];
    v.x = tf32_rna(v.x); v.y = tf32_rna(v.y); v.z = tf32_rna(v.z); v.w = tf32_rna(v.w);
    reinterpret_cast<float4*>(g_W)[idx] = v;
}

// ========================= kernel 3: tf32 GEMM =========================
// C[4096,1024] = g_A[4096,8192] * g_W[1024,8192]^T + bias
// CTA tile 128x128x32; 8 warps (2 M x 4 N); warp tile 64x32 -> 4x4 m16n8k8 MMAs.
constexpr int TILE_K  = 32;
constexpr int STAGES  = 4;
constexpr int KCHUNKS = KDIM / TILE_K;          // 256
constexpr int AROW    = 36;                      // padded floats per SMEM row (conflict-free)
constexpr int STAGE_FLOATS = 128 * AROW * 2;     // A tile + B tile
constexpr int DYN_SMEM = STAGES * STAGE_FLOATS * 4;  // 147456 bytes

__global__ void __launch_bounds__(256, 1) gemm_kernel(const float* __restrict__ bias,
                                                      float* __restrict__ out) {
    extern __shared__ float smem[];
    const int tid  = threadIdx.x;
    const int wid  = tid >> 5;
    const int lane = tid & 31;
    const int g    = lane >> 2;    // groupID (0..7)
    const int tg   = lane & 3;     // threadID in group (0..3)
    const int nTile = blockIdx.x;  // 0..7  (x-fastest: share A block-row via L2)
    const int mTile = blockIdx.y;  // 0..31
    const int mbase = (wid >> 2) * 64;  // warp M offset in CTA tile
    const int nbase = (wid & 3) * 32;   // warp N offset in CTA tile

    const float* __restrict__ Ag = g_A + (size_t)mTile * 128 * KDIM;
    const float* __restrict__ Bg = g_W + (size_t)nTile * 128 * KDIM;

    // Per-thread copy assignment: 4 (row,seg) pairs for A, same for B.
    // idx = tid + i*256; row = idx>>3 (0..127), seg = idx&7 (8 x 16B per 32-float row).
    float acc[4][4][4];
#pragma unroll
    for (int mt = 0; mt < 4; mt++)
#pragma unroll
        for (int nt = 0; nt < 4; nt++)
#pragma unroll
            for (int j = 0; j < 4; j++) acc[mt][nt][j] = 0.0f;

    // ---- async copy of one K-chunk into stage s ----
    auto issue = [&](int kc, int s) {
        float* As = smem + s * STAGE_FLOATS;
        float* Bs = As + 128 * AROW;
#pragma unroll
        for (int i = 0; i < 4; i++) {
            int idx = tid + i * 256;
            int row = idx >> 3;
            int seg = idx & 7;
            uint32_t da = smem_u32(As + row * AROW + seg * 4);
            CP_ASYNC_CG16(da, Ag + (size_t)row * KDIM + kc * TILE_K + seg * 4);
            uint32_t db = smem_u32(Bs + row * AROW + seg * 4);
            CP_ASYNC_CG16(db, Bg + (size_t)row * KDIM + kc * TILE_K + seg * 4);
        }
        CP_ASYNC_COMMIT();
    };

    // Prologue: prefetch STAGES-1 chunks.
#pragma unroll
    for (int s = 0; s < STAGES - 1; s++) issue(s, s);

#pragma unroll 1
    for (int kc = 0; kc < KCHUNKS; kc++) {
        CP_ASYNC_WAIT(STAGES - 2);   // chunk kc's copies (this thread's) are done
        __syncthreads();             // -> everyone's copies for stage kc are done

        // Refill the slot freed by last iteration's compute.
        int nk = kc + STAGES - 1;
        if (nk < KCHUNKS) issue(nk, nk & (STAGES - 1));
        else CP_ASYNC_COMMIT();      // keep group count consistent

        const float* As = smem + (kc & (STAGES - 1)) * STAGE_FLOATS;
        const float* Bs = As + 128 * AROW;

#pragma unroll
        for (int ks = 0; ks < 4; ks++) {
            const int k = ks * 8;
            uint32_t af[4][4];
            uint32_t bf[4][2];
#pragma unroll
            for (int mt = 0; mt < 4; mt++) {
                const float* ap = As + (mbase + mt * 16 + g) * AROW + k + tg;
                af[mt][0] = __float_as_uint(ap[0]);
                af[mt][1] = __float_as_uint(ap[8 * AROW]);
                af[mt][2] = __float_as_uint(ap[4]);
                af[mt][3] = __float_as_uint(ap[8 * AROW + 4]);
            }
#pragma unroll
            for (int nt = 0; nt < 4; nt++) {
                const float* bp = Bs + (nbase + nt * 8 + g) * AROW + k + tg;
                bf[nt][0] = __float_as_uint(bp[0]);
                bf[nt][1] = __float_as_uint(bp[4]);
            }
#pragma unroll
            for (int mt = 0; mt < 4; mt++)
#pragma unroll
                for (int nt = 0; nt < 4; nt++)
                    MMA_TF32(acc[mt][nt], af[mt], bf[nt]);
        }
    }

    // ------------------------------ epilogue ------------------------------
    float bv[4][2];
#pragma unroll
    for (int nt = 0; nt < 4; nt++) {
        int col = nTile * 128 + nbase + nt * 8 + 2 * tg;
        bv[nt][0] = bias[col];
        bv[nt][1] = bias[col + 1];
    }
#pragma unroll
    for (int mt = 0; mt < 4; mt++) {
        int row0 = mTile * 128 + mbase + mt * 16 + g;
#pragma unroll
        for (int nt = 0; nt < 4; nt++) {
            int col = nTile * 128 + nbase + nt * 8 + 2 * tg;
            float2 v0, v1;
            v0.x = acc[mt][nt][0] + bv[nt][0];
            v0.y = acc[mt][nt][1] + bv[nt][1];
            v1.x = acc[mt][nt][2] + bv[nt][0];
            v1.y = acc[mt][nt][3] + bv[nt][1];
            *reinterpret_cast<float2*>(out + (size_t)row0 * OUTF + col) = v0;
            *reinterpret_cast<float2*>(out + (size_t)(row0 + 8) * OUTF + col) = v1;
        }
    }
}

// ============================ launcher =================================
extern "C" void kernel_launch(void* const* d_in, const int* in_sizes, int n_in,
                              void* d_out, int out_size) {
    const float* x    = (const float*)d_in[0];
    const float* w    = (const float*)d_in[1];
    const float* bias = (const float*)d_in[2];
    float* out        = (float*)d_out;

    cudaFuncSetAttribute(gemm_kernel, cudaFuncAttributeMaxDynamicSharedMemorySize, DYN_SMEM);

    basis_kernel<<<(BATCH * INF + 255) / 256, 256>>>(x);
    wconv_kernel<<<((OUTF * KDIM) / 4 + 255) / 256, 256>>>(w);
    gemm_kernel<<<dim3(OUTF / 128, BATCH / 128), 256, DYN_SMEM>>>(bias, out);
}

// round 3
// speedup vs baseline: 2.4677x; 2.4677x over previous
#include <cuda_runtime.h>
#include <cuda_fp16.h>
#include <cstdint>

// ============================ problem sizes ============================
#define BATCH 4096
#define INF   1024
#define OUTF  1024
#define KBASIS 8
#define KDIM  (INF * KBASIS)   // 8192

// ======================= device scratch (no allocs) ====================
__device__ __half g_A[(size_t)BATCH * KDIM];   // fp16 basis  [4096 x 8192]
__device__ __half g_W[(size_t)OUTF * KDIM];    // fp16 weights [1024 x 8192]

// ============================ PTX helpers ==============================
__device__ __forceinline__ uint32_t smem_u32(const void* p) {
    uint32_t a;
    asm("{ .reg .u64 t; cvta.to.shared.u64 t, %1; cvt.u32.u64 %0, t; }" : "=r"(a) : "l"(p));
    return a;
}

#define CP_ASYNC_CG16(smem, gptr) \
    asm volatile("cp.async.cg.shared.global [%0], [%1], 16;" :: "r"(smem), "l"(gptr) : "memory")

#define CP_ASYNC_COMMIT() \
    asm volatile("cp.async.commit_group;" ::: "memory")

#define CP_ASYNC_WAIT(n) \
    asm volatile("cp.async.wait_group %0;" :: "n"(n) : "memory")

#define LDSM_X4(r0, r1, r2, r3, addr) \
    asm volatile("ldmatrix.sync.aligned.m8n8.x4.shared.b16 {%0,%1,%2,%3}, [%4];" \
        : "=r"(r0), "=r"(r1), "=r"(r2), "=r"(r3) : "r"(addr))

// m16n8k16 fp16 MMA (row-major A, col-major B), fp32 accumulate in place.
#define MMA_F16(d, a, b) \
    asm volatile("mma.sync.aligned.m16n8k16.row.col.f32.f16.f16.f32 " \
        "{%0,%1,%2,%3}, {%4,%5,%6,%7}, {%8,%9}, {%0,%1,%2,%3};" \
        : "+f"((d)[0]), "+f"((d)[1]), "+f"((d)[2]), "+f"((d)[3]) \
        : "r"((a)[0]), "r"((a)[1]), "r"((a)[2]), "r"((a)[3]), \
          "r"((b)[0]), "r"((b)[1]))

// ======================= kernel 1: Chebyshev basis =====================
__global__ void __launch_bounds__(256) basis_kernel(const float* __restrict__ x) {
    int idx = blockIdx.x * blockDim.x + threadIdx.x;   // idx = b*INF + i
    if (idx >= BATCH * INF) return;
    float t = tanhf(x[idx]);
    float T[KBASIS];
    T[0] = 1.0f;
    T[1] = t;
#pragma unroll
    for (int k = 2; k < KBASIS; k++) T[k] = 2.0f * t * T[k - 1] - T[k - 2];

    __half2 h[4];
#pragma unroll
    for (int k = 0; k < 4; k++)
        h[k] = __floats2half2_rn(T[2 * k], T[2 * k + 1]);
    *reinterpret_cast<uint4*>(&g_A[(size_t)idx * KBASIS]) = *reinterpret_cast<uint4*>(h);
}

// ===================== kernel 2: weights -> fp16 =======================
__global__ void __launch_bounds__(256) wconv_kernel(const float* __restrict__ w) {
    int idx = blockIdx.x * blockDim.x + threadIdx.x;   // 8-float group index
    if (idx >= (OUTF * KDIM) / 8) return;
    const float4* src = reinterpret_cast<const float4*>(w) + 2 * idx;
    float4 v0 = src[0], v1 = src[1];
    __half2 h[4];
    h[0] = __floats2half2_rn(v0.x, v0.y);
    h[1] = __floats2half2_rn(v0.z, v0.w);
    h[2] = __floats2half2_rn(v1.x, v1.y);
    h[3] = __floats2half2_rn(v1.z, v1.w);
    reinterpret_cast<uint4*>(g_W)[idx] = *reinterpret_cast<uint4*>(h);
}

// ========================= kernel 3: fp16 GEMM =========================
// C[4096,1024] = g_A[4096,8192] * g_W[1024,8192]^T + bias
// CTA tile 128x128, K-chunk 64 halves (128B rows, XOR-swizzled).
// 8 warps (2 M x 4 N); warp tile 64x32 -> 4mt x 4nt m16n8k16 MMAs per k16-step.
constexpr int TILE_K  = 64;                          // halves per chunk
constexpr int STAGES  = 4;
constexpr int KCHUNKS = KDIM / TILE_K;               // 128
constexpr int MAT_BYTES   = 128 * 128;               // 16 KB: 128 rows x 128B
constexpr int STAGE_BYTES = 2 * MAT_BYTES;           // A + B
constexpr int DYN_SMEM    = STAGES * STAGE_BYTES;    // 128 KB

__global__ void __launch_bounds__(256, 1) gemm_kernel(const float* __restrict__ bias,
                                                      float* __restrict__ out) {
    extern __shared__ char smem[];
    const int tid  = threadIdx.x;
    const int wid  = tid >> 5;
    const int lane = tid & 31;
    const int g    = lane >> 2;    // groupID (0..7)
    const int tg   = lane & 3;     // threadID in group (0..3)
    const int nTile = blockIdx.x;  // 0..7  (x-fastest: share A block-row via L2)
    const int mTile = blockIdx.y;  // 0..31
    const int mbase = (wid >> 2) * 64;  // warp M offset in CTA tile
    const int nbase = (wid & 3) * 32;   // warp N offset in CTA tile

    const __half* __restrict__ Ag = g_A + (size_t)mTile * 128 * KDIM;
    const __half* __restrict__ Bg = g_W + (size_t)nTile * 128 * KDIM;
    const uint32_t sbase = smem_u32(smem);

    float acc[4][4][4];
#pragma unroll
    for (int mt = 0; mt < 4; mt++)
#pragma unroll
        for (int nt = 0; nt < 4; nt++)
#pragma unroll
            for (int j = 0; j < 4; j++) acc[mt][nt][j] = 0.0f;

    // ---- per-thread ldmatrix lane addressing (within a stage) ----
    // A: lanes 0-15 -> rows 0-15 (khalf 0), lanes 16-31 -> rows 0-15 (khalf 1)
    const int arow  = mbase + (lane & 15);
    const int akh   = lane >> 4;
    const int aswz  = arow & 7;
    // B: lanes 0-7 n0-7 kh0; 8-15 n0-7 kh1; 16-23 n8-15 kh0; 24-31 n8-15 kh1
    const int brow0 = nbase + (lane & 7) + ((lane >> 4) & 1) * 8;
    const int bkh   = (lane >> 3) & 1;
    const int bswz  = brow0 & 7;

    // ---- async copy of one K-chunk into stage s ----
    auto issue = [&](int kc, int s) {
        const uint32_t so = sbase + (uint32_t)s * STAGE_BYTES;
#pragma unroll
        for (int i = 0; i < 4; i++) {   // A: 1024 16B segs
            int idx = tid + i * 256;
            int row = idx >> 3;
            int seg = idx & 7;
            uint32_t dst = so + row * 128 + ((seg ^ (row & 7)) * 16);
            CP_ASYNC_CG16(dst, Ag + (size_t)row * KDIM + kc * TILE_K + seg * 8);
        }
#pragma unroll
        for (int i = 0; i < 4; i++) {   // B: 1024 16B segs
            int idx = tid + i * 256;
            int row = idx >> 3;
            int seg = idx & 7;
            uint32_t dst = so + MAT_BYTES + row * 128 + ((seg ^ (row & 7)) * 16);
            CP_ASYNC_CG16(dst, Bg + (size_t)row * KDIM + kc * TILE_K + seg * 8);
        }
        CP_ASYNC_COMMIT();
    };

    // Prologue: prefetch STAGES-1 chunks.
#pragma unroll
    for (int s = 0; s < STAGES - 1; s++) issue(s, s);

#pragma unroll 1
    for (int kc = 0; kc < KCHUNKS; kc++) {
        CP_ASYNC_WAIT(STAGES - 2);
        __syncthreads();

        int nk = kc + STAGES - 1;
        if (nk < KCHUNKS) issue(nk, nk & (STAGES - 1));
        else CP_ASYNC_COMMIT();      // keep group count consistent

        const uint32_t so = sbase + (uint32_t)(kc & (STAGES - 1)) * STAGE_BYTES;

#pragma unroll
        for (int ks = 0; ks < TILE_K / 16; ks++) {   // 4 k16-steps
            uint32_t af[4][4];
            uint32_t bf[2][4];
#pragma unroll
            for (int mt = 0; mt < 4; mt++) {
                uint32_t addr = so + (arow + mt * 16) * 128
                              + (((ks * 2 + akh) ^ aswz) * 16);
                LDSM_X4(af[mt][0], af[mt][1], af[mt][2], af[mt][3], addr);
            }
#pragma unroll
            for (int pair = 0; pair < 2; pair++) {
                uint32_t addr = so + MAT_BYTES + (brow0 + pair * 16) * 128
                              + (((ks * 2 + bkh) ^ bswz) * 16);
                LDSM_X4(bf[pair][0], bf[pair][1], bf[pair][2], bf[pair][3], addr);
            }
#pragma unroll
            for (int mt = 0; mt < 4; mt++)
#pragma unroll
                for (int nt = 0; nt < 4; nt++)
                    MMA_F16(acc[mt][nt], af[mt], &bf[nt >> 1][(nt & 1) * 2]);
        }
    }

    // ------------------------------ epilogue ------------------------------
    float bv[4][2];
#pragma unroll
    for (int nt = 0; nt < 4; nt++) {
        int col = nTile * 128 + nbase + nt * 8 + 2 * tg;
        bv[nt][0] = bias[col];
        bv[nt][1] = bias[col + 1];
    }
#pragma unroll
    for (int mt = 0; mt < 4; mt++) {
        int row0 = mTile * 128 + mbase + mt * 16 + g;
#pragma unroll
        for (int nt = 0; nt < 4; nt++) {
            int col = nTile * 128 + nbase + nt * 8 + 2 * tg;
            float2 v0, v1;
            v0.x = acc[mt][nt][0] + bv[nt][0];
            v0.y = acc[mt][nt][1] + bv[nt][1];
            v1.x = acc[mt][nt][2] + bv[nt][0];
            v1.y = acc[mt][nt][3] + bv[nt][1];
            *reinterpret_cast<float2*>(out + (size_t)row0 * OUTF + col) = v0;
            *reinterpret_cast<float2*>(out + (size_t)(row0 + 8) * OUTF + col) = v1;
        }
    }
}

// ============================ launcher =================================
extern "C" void kernel_launch(void* const* d_in, const int* in_sizes, int n_in,
                              void* d_out, int out_size) {
    const float* x    = (const float*)d_in[0];
    const float* w    = (const float*)d_in[1];
    const float* bias = (const float*)d_in[2];
    float* out        = (float*)d_out;

    cudaFuncSetAttribute(gemm_kernel, cudaFuncAttributeMaxDynamicSharedMemorySize, DYN_SMEM);

    basis_kernel<<<(BATCH * INF + 255) / 256, 256>>>(x);
    wconv_kernel<<<((OUTF * KDIM) / 8 + 255) / 256, 256>>>(w);
    gemm_kernel<<<dim3(OUTF / 128, BATCH / 128), 256, DYN_SMEM>>>(bias, out);
}